// round 16
// baseline (speedup 1.0000x reference)
#include <cuda_runtime.h>
#include <cuda_fp16.h>
#include <math.h>
#include <stdint.h>

// Problem constants (fixed-shape problem)
#define NN      50000
#define EE      800000
#define ETOT    (EE + NN)      // self-loops appended
#define IN_CH   512
#define HID     32
#define HEADS   8
#define D1      (HID * HEADS)  // 256
#define NCLS    40
#define NEG_SLOPE 0.2f
#define NB_SCAN ((NN + 255) / 256)   // 196

// ---------------- scratch (device globals, no allocs allowed) ----------------
__device__ __align__(128) __half g_h1h[NN * D1];         // 25.6 MB (fp16 h1)
__device__ __align__(128) __half g_out1h[NN * D1];       // 25.6 MB (fp16 post-ELU)
__device__ __align__(128) float g_al_src[NN * HEADS];
__device__ __align__(128) float g_al_dst[NN * HEADS];
__device__ __align__(128) __half g_h2h[NN * NCLS];       // 4 MB (fp16 h2)
__device__ __align__(128) float g_al2s[NN];
__device__ __align__(128) float g_al2d[NN];
// CSR-by-dst
__device__ __align__(128) int g_deg[NN];
__device__ __align__(128) int g_off[NN];
__device__ __align__(128) int g_wpos[NN];
__device__ int g_esrc[ETOT];

// ---------------- helpers ----------------
__device__ __forceinline__ float leaky(float x) {
    return x > 0.0f ? x : NEG_SLOPE * x;
}

__device__ __forceinline__ uint32_t h2_as_u32(__half2 h) {
    return *reinterpret_cast<uint32_t*>(&h);
}

__device__ __forceinline__ void mma_f16(float c[4], uint32_t a0, uint32_t a1,
                                        uint32_t a2, uint32_t a3,
                                        uint32_t b0, uint32_t b1) {
    asm volatile(
        "mma.sync.aligned.m16n8k16.row.col.f32.f16.f16.f32 "
        "{%0,%1,%2,%3}, {%4,%5,%6,%7}, {%8,%9}, {%0,%1,%2,%3};\n"
        : "+f"(c[0]), "+f"(c[1]), "+f"(c[2]), "+f"(c[3])
        : "r"(a0), "r"(a1), "r"(a2), "r"(a3), "r"(b0), "r"(b1));
}

__device__ __forceinline__ void ldsm_x4(uint32_t& r0, uint32_t& r1,
                                        uint32_t& r2, uint32_t& r3,
                                        uint32_t addr) {
    asm volatile("ldmatrix.sync.aligned.m8n8.x4.shared.b16 {%0,%1,%2,%3}, [%4];"
                 : "=r"(r0), "=r"(r1), "=r"(r2), "=r"(r3) : "r"(addr));
}

__device__ __forceinline__ void ldsm_x2_trans(uint32_t& r0, uint32_t& r1,
                                              uint32_t addr) {
    asm volatile("ldmatrix.sync.aligned.m8n8.x2.trans.shared.b16 {%0,%1}, [%2];"
                 : "=r"(r0), "=r"(r1) : "r"(addr));
}

// =====================================================================
// fp16 HMMA GEMM1 (proven R12): C[M,256] = A[M,512] @ B[512,256].
// =====================================================================
__global__ __launch_bounds__(256)
void fp16_gemm1(const float* __restrict__ A, const float* __restrict__ B,
                __half* __restrict__ C, int M,
                const float* __restrict__ as1, const float* __restrict__ ad1,
                float* __restrict__ als, float* __restrict__ ald) {
    constexpr int KTOT = IN_CH;    // 512
    constexpr int NCOLS = D1;      // 256
    constexpr int ASTR = 40;
    constexpr int BSTR = 136;
    __shared__ __align__(16) __half As[2][128][ASTR];
    __shared__ __align__(16) __half Bs[2][32][BSTR];

    const int tid = threadIdx.x;
    const int lane = tid & 31;
    const int warpId = tid >> 5;
    const int br = blockIdx.y;
    const int bc = blockIdx.x;

    const int wm = (warpId & 3) * 32;
    const int wn = (warpId >> 2) * 64;
    const int g = lane >> 2;
    const int t = lane & 3;

    float acc[2][8][4];
#pragma unroll
    for (int mi = 0; mi < 2; mi++)
#pragma unroll
        for (int ni = 0; ni < 8; ni++)
#pragma unroll
            for (int r = 0; r < 4; r++) acc[mi][ni][r] = 0.0f;

    const int a_m = tid >> 3;
    const int a_k = (tid & 7) * 4;
    const int b_n = (tid & 31) * 4;
    const int b_k = tid >> 5;

    float4 ra[4], rb[4];

    auto loadA = [&](int r, int k0) -> float4 {
        int grow = br * 128 + r * 32 + a_m;
        if (grow >= M) return make_float4(0.f, 0.f, 0.f, 0.f);
        return *reinterpret_cast<const float4*>(A + (size_t)grow * KTOT + k0 + a_k);
    };
    auto loadB = [&](int r, int k0) -> float4 {
        return *reinterpret_cast<const float4*>(
            B + (size_t)(k0 + r * 8 + b_k) * NCOLS + bc * 128 + b_n);
    };
    auto stageChunk = [&](int nb) {
#pragma unroll
        for (int r = 0; r < 4; r++) {
            __half2 h0 = __float22half2_rn(make_float2(ra[r].x, ra[r].y));
            __half2 h1 = __float22half2_rn(make_float2(ra[r].z, ra[r].w));
            uint2 u = make_uint2(h2_as_u32(h0), h2_as_u32(h1));
            *reinterpret_cast<uint2*>(&As[nb][r * 32 + a_m][a_k]) = u;
        }
#pragma unroll
        for (int r = 0; r < 4; r++) {
            __half2 h0 = __float22half2_rn(make_float2(rb[r].x, rb[r].y));
            __half2 h1 = __float22half2_rn(make_float2(rb[r].z, rb[r].w));
            uint2 u = make_uint2(h2_as_u32(h0), h2_as_u32(h1));
            *reinterpret_cast<uint2*>(&Bs[nb][r * 8 + b_k][b_n]) = u;
        }
    };

#pragma unroll
    for (int r = 0; r < 4; r++) { ra[r] = loadA(r, 0); rb[r] = loadB(r, 0); }
    stageChunk(0);
    __syncthreads();
#pragma unroll
    for (int r = 0; r < 4; r++) { ra[r] = loadA(r, 32); rb[r] = loadB(r, 32); }

    const int lg = lane >> 3;
    const int li = lane & 7;
    const int a_frow = ((lg & 1) << 3) + li;
    const int a_fcol = (lg >> 1) << 3;
    const int b_frow = ((lane >> 3) & 1) * 8 + li;

    int buf = 0;
    for (int k0 = 0; k0 < KTOT; k0 += 32) {
        bool has_next = (k0 + 32 < KTOT);
        if (has_next) stageChunk(buf ^ 1);
        if (k0 + 64 < KTOT) {
#pragma unroll
            for (int r = 0; r < 4; r++) { ra[r] = loadA(r, k0 + 64); rb[r] = loadB(r, k0 + 64); }
        }

#pragma unroll
        for (int ks = 0; ks < 2; ks++) {
            const int kk = ks * 16;
            uint32_t a[2][4];
#pragma unroll
            for (int mi = 0; mi < 2; mi++) {
                uint32_t ad = (uint32_t)__cvta_generic_to_shared(
                    &As[buf][wm + mi * 16 + a_frow][kk + a_fcol]);
                ldsm_x4(a[mi][0], a[mi][1], a[mi][2], a[mi][3], ad);
            }
#pragma unroll
            for (int ni = 0; ni < 8; ni++) {
                uint32_t bd = (uint32_t)__cvta_generic_to_shared(
                    &Bs[buf][kk + b_frow][wn + ni * 8]);
                uint32_t b0, b1;
                ldsm_x2_trans(b0, b1, bd);
                mma_f16(acc[0][ni], a[0][0], a[0][1], a[0][2], a[0][3], b0, b1);
                mma_f16(acc[1][ni], a[1][0], a[1][1], a[1][2], a[1][3], b0, b1);
            }
        }
        if (has_next) {
            __syncthreads();
            buf ^= 1;
        }
    }

    // epilogue: store C (fp16)
#pragma unroll
    for (int mi = 0; mi < 2; mi++) {
        int row0 = br * 128 + wm + mi * 16 + g;
        int row1 = row0 + 8;
#pragma unroll
        for (int ni = 0; ni < 8; ni++) {
            int col = bc * 128 + wn + ni * 8 + 2 * t;
            if (row0 < M)
                *reinterpret_cast<__half2*>(C + (size_t)row0 * NCOLS + col) =
                    __float22half2_rn(make_float2(acc[mi][ni][0], acc[mi][ni][1]));
            if (row1 < M)
                *reinterpret_cast<__half2*>(C + (size_t)row1 * NCOLS + col) =
                    __float22half2_rn(make_float2(acc[mi][ni][2], acc[mi][ni][3]));
        }
    }

    // fused per-head attention dots (32-col head groups)
#pragma unroll
    for (int mi = 0; mi < 2; mi++) {
#pragma unroll
        for (int hl = 0; hl < 2; hl++) {
            float ps0 = 0.f, ps1 = 0.f, pd0 = 0.f, pd1 = 0.f;
#pragma unroll
            for (int nq = 0; nq < 4; nq++) {
                int ni = hl * 4 + nq;
                int gcol = bc * 128 + wn + ni * 8 + 2 * t;
                float a0 = as1[gcol], a1 = as1[gcol + 1];
                float d0 = ad1[gcol], d1 = ad1[gcol + 1];
                ps0 += acc[mi][ni][0] * a0 + acc[mi][ni][1] * a1;
                ps1 += acc[mi][ni][2] * a0 + acc[mi][ni][3] * a1;
                pd0 += acc[mi][ni][0] * d0 + acc[mi][ni][1] * d1;
                pd1 += acc[mi][ni][2] * d0 + acc[mi][ni][3] * d1;
            }
#pragma unroll
            for (int off = 1; off < 4; off <<= 1) {
                ps0 += __shfl_xor_sync(0xffffffffu, ps0, off);
                ps1 += __shfl_xor_sync(0xffffffffu, ps1, off);
                pd0 += __shfl_xor_sync(0xffffffffu, pd0, off);
                pd1 += __shfl_xor_sync(0xffffffffu, pd1, off);
            }
            if (t == 0) {
                int head = ((bc * 128 + wn) >> 5) + hl;
                int row0 = br * 128 + wm + mi * 16 + g;
                int row1 = row0 + 8;
                if (row0 < M) {
                    als[(size_t)row0 * HEADS + head] = ps0;
                    ald[(size_t)row0 * HEADS + head] = pd0;
                }
                if (row1 < M) {
                    als[(size_t)row1 * HEADS + head] = ps1;
                    ald[(size_t)row1 * HEADS + head] = pd1;
                }
            }
        }
    }
}

// =====================================================================
// fp16 HMMA GEMM2 (R15): C[M,40] = A[M,256](fp16) @ B[256,40].
// BM=128, 8 warps x 16 rows, N tile = 40 exact. Fused per-row al2 dots.
// =====================================================================
__global__ __launch_bounds__(256)
void fp16_gemm2(const __half* __restrict__ A, const float* __restrict__ B,
                __half* __restrict__ C, int M,
                const float* __restrict__ as2, const float* __restrict__ ad2,
                float* __restrict__ als, float* __restrict__ ald) {
    constexpr int KTOT = D1;       // 256
    constexpr int NCOLS = NCLS;    // 40
    constexpr int BM = 128;
    constexpr int NI = 5;
    constexpr int ASTR = 40;
    constexpr int BSTR = 72;
    __shared__ __align__(16) __half As[BM][ASTR];
    __shared__ __align__(16) __half Bs[32][BSTR];

    const int tid = threadIdx.x;
    const int lane = tid & 31;
    const int warpId = tid >> 5;
    const int br = blockIdx.y;

    const int wm = warpId * 16;
    const int g = lane >> 2;
    const int t = lane & 3;

    float acc[NI][4];
#pragma unroll
    for (int ni = 0; ni < NI; ni++)
#pragma unroll
        for (int r = 0; r < 4; r++) acc[ni][r] = 0.0f;

    const int a_m = tid >> 3;
    const int a_k = (tid & 7) * 4;
    const int b_n = (tid & 15) * 4;
    const int b_k = tid >> 4;

    uint2 ra[4];
    float4 rb[2];

    auto loadA = [&](int r, int k0) -> uint2 {
        int grow = br * BM + r * 32 + a_m;
        if (grow >= M) return make_uint2(0u, 0u);
        return *reinterpret_cast<const uint2*>(A + (size_t)grow * KTOT + k0 + a_k);
    };
    auto loadBg = [&](int r, int k0) -> float4 {
        if (b_n >= NCOLS) return make_float4(0.f, 0.f, 0.f, 0.f);
        return *reinterpret_cast<const float4*>(
            B + (size_t)(k0 + r * 16 + b_k) * NCOLS + b_n);
    };
    auto stageChunk = [&]() {
#pragma unroll
        for (int r = 0; r < 4; r++)
            *reinterpret_cast<uint2*>(&As[r * 32 + a_m][a_k]) = ra[r];
#pragma unroll
        for (int r = 0; r < 2; r++) {
            __half2 h0 = __float22half2_rn(make_float2(rb[r].x, rb[r].y));
            __half2 h1 = __float22half2_rn(make_float2(rb[r].z, rb[r].w));
            uint2 u = make_uint2(h2_as_u32(h0), h2_as_u32(h1));
            *reinterpret_cast<uint2*>(&Bs[r * 16 + b_k][b_n]) = u;
        }
    };

#pragma unroll
    for (int r = 0; r < 4; r++) ra[r] = loadA(r, 0);
#pragma unroll
    for (int r = 0; r < 2; r++) rb[r] = loadBg(r, 0);

    const int lg = lane >> 3;
    const int li = lane & 7;
    const int a_frow = ((lg & 1) << 3) + li;
    const int a_fcol = (lg >> 1) << 3;
    const int b_frow = ((lane >> 3) & 1) * 8 + li;

    for (int k0 = 0; k0 < KTOT; k0 += 32) {
        stageChunk();
        __syncthreads();

        if (k0 + 32 < KTOT) {
#pragma unroll
            for (int r = 0; r < 4; r++) ra[r] = loadA(r, k0 + 32);
#pragma unroll
            for (int r = 0; r < 2; r++) rb[r] = loadBg(r, k0 + 32);
        }

#pragma unroll
        for (int ks = 0; ks < 2; ks++) {
            const int kk = ks * 16;
            uint32_t a0, a1, a2, a3;
            uint32_t ad = (uint32_t)__cvta_generic_to_shared(
                &As[wm + a_frow][kk + a_fcol]);
            ldsm_x4(a0, a1, a2, a3, ad);
#pragma unroll
            for (int ni = 0; ni < NI; ni++) {
                uint32_t bd = (uint32_t)__cvta_generic_to_shared(
                    &Bs[kk + b_frow][ni * 8]);
                uint32_t b0, b1;
                ldsm_x2_trans(b0, b1, bd);
                mma_f16(acc[ni], a0, a1, a2, a3, b0, b1);
            }
        }
        __syncthreads();
    }

    // epilogue: store C (fp16)
    {
        int row0 = br * BM + wm + g;
        int row1 = row0 + 8;
#pragma unroll
        for (int ni = 0; ni < NI; ni++) {
            int col = ni * 8 + 2 * t;
            if (row0 < M)
                *reinterpret_cast<__half2*>(C + (size_t)row0 * NCOLS + col) =
                    __float22half2_rn(make_float2(acc[ni][0], acc[ni][1]));
            if (row1 < M)
                *reinterpret_cast<__half2*>(C + (size_t)row1 * NCOLS + col) =
                    __float22half2_rn(make_float2(acc[ni][2], acc[ni][3]));
        }
    }

    // fused per-row attention dots
    {
        float ps0 = 0.f, ps1 = 0.f, pd0 = 0.f, pd1 = 0.f;
#pragma unroll
        for (int ni = 0; ni < NI; ni++) {
            int col = ni * 8 + 2 * t;
            float a0 = as2[col], a1 = as2[col + 1];
            float d0 = ad2[col], d1 = ad2[col + 1];
            ps0 += acc[ni][0] * a0 + acc[ni][1] * a1;
            ps1 += acc[ni][2] * a0 + acc[ni][3] * a1;
            pd0 += acc[ni][0] * d0 + acc[ni][1] * d1;
            pd1 += acc[ni][2] * d0 + acc[ni][3] * d1;
        }
#pragma unroll
        for (int off = 1; off < 4; off <<= 1) {
            ps0 += __shfl_xor_sync(0xffffffffu, ps0, off);
            ps1 += __shfl_xor_sync(0xffffffffu, ps1, off);
            pd0 += __shfl_xor_sync(0xffffffffu, pd0, off);
            pd1 += __shfl_xor_sync(0xffffffffu, pd1, off);
        }
        if (t == 0) {
            int row0 = br * BM + wm + g;
            int row1 = row0 + 8;
            if (row0 < M) { als[row0] = ps0; ald[row0] = pd0; }
            if (row1 < M) { als[row1] = ps1; ald[row1] = pd1; }
        }
    }
}

// ================= CSR build =================
__global__ void zero_deg_kernel() {
    int i = blockIdx.x * blockDim.x + threadIdx.x;
    if (i < NN) g_deg[i] = 0;
}

__global__ void hist_kernel(const int* __restrict__ ei) {
    int e = blockIdx.x * blockDim.x + threadIdx.x;
    if (e >= ETOT) return;
    int dst = (e < EE) ? ei[EE + e] : e - EE;
    atomicAdd(&g_deg[dst], 1);
}

// Single-block exclusive scan of g_deg[NN] -> g_off, g_wpos.
// 1024 threads, tiles of 8192 (8 consecutive elements per thread).
__global__ __launch_bounds__(1024)
void scan_all_kernel() {
    __shared__ int wsum[32];
    __shared__ int tile_total_sh;
    const int tid = threadIdx.x;
    const int lane = tid & 31;
    const int wid = tid >> 5;

    int base = 0;
    for (int t0 = 0; t0 < NN; t0 += 8192) {
        int idx = t0 + tid * 8;
        int v[8];
#pragma unroll
        for (int i = 0; i < 8; i++) {
            int j = idx + i;
            v[i] = (j < NN) ? g_deg[j] : 0;
        }
        // serial exclusive scan within thread; s = thread total
        int s = 0;
#pragma unroll
        for (int i = 0; i < 8; i++) { int tv = v[i]; v[i] = s; s += tv; }
        // inclusive warp scan of thread totals
        int inc = s;
#pragma unroll
        for (int off = 1; off < 32; off <<= 1) {
            int u = __shfl_up_sync(0xffffffffu, inc, off);
            if (lane >= off) inc += u;
        }
        int excl = inc - s;
        if (lane == 31) wsum[wid] = inc;
        __syncthreads();
        if (wid == 0) {
            int w = wsum[lane];
            int winc = w;
#pragma unroll
            for (int off = 1; off < 32; off <<= 1) {
                int u = __shfl_up_sync(0xffffffffu, winc, off);
                if (lane >= off) winc += u;
            }
            wsum[lane] = winc - w;          // exclusive warp base
            if (lane == 31) tile_total_sh = winc;
        }
        __syncthreads();
        int pre = base + wsum[wid] + excl;
#pragma unroll
        for (int i = 0; i < 8; i++) {
            int j = idx + i;
            if (j < NN) {
                int o = pre + v[i];
                g_off[j] = o;
                g_wpos[j] = o;
            }
        }
        base += tile_total_sh;
        __syncthreads();   // protect wsum / tile_total_sh before next tile
    }
}

__global__ void scatter_kernel(const int* __restrict__ ei) {
    int e = blockIdx.x * blockDim.x + threadIdx.x;
    if (e >= ETOT) return;
    int src, dst;
    if (e < EE) { src = ei[e]; dst = ei[EE + e]; }
    else        { src = dst = e - EE; }
    int pos = atomicAdd(&g_wpos[dst], 1);
    g_esrc[pos] = src;
}

// ================= fused softmax + aggregation, layer 1 =================
// One warp per dst. Groups of 4 edges: p staged across lanes
// (lane = edge*8+head), one exp per (edge,head); exp off serial chain.
__global__ __launch_bounds__(256)
void fused_agg1(const float* __restrict__ b1) {
    int dst = (blockIdx.x * 256 + threadIdx.x) >> 5;
    int lane = threadIdx.x & 31;
    if (dst >= NN) return;
    int head = lane >> 2;
    int h8 = lane & 7;
    float ald_stage = g_al_dst[(size_t)dst * 8 + h8];
    int start = g_off[dst];
    int deg = g_deg[dst];

    float acc[8];
#pragma unroll
    for (int j = 0; j < 8; j++) acc[j] = 0.0f;
    float denom = 0.0f;

    for (int base = 0; base < deg; base += 32) {
        int n = min(32, deg - base);
        int r_src = (lane < n) ? g_esrc[start + base + lane] : 0;

        int jj = 0;
        for (; jj + 3 < n; jj += 4) {
            int le = jj + (lane >> 3);
            int src_st = __shfl_sync(0xffffffffu, r_src, le);
            float p_st = __expf(leaky(g_al_src[(size_t)src_st * 8 + h8] + ald_stage));
            int s0 = __shfl_sync(0xffffffffu, r_src, jj);
            int s1 = __shfl_sync(0xffffffffu, r_src, jj + 1);
            int s2 = __shfl_sync(0xffffffffu, r_src, jj + 2);
            int s3 = __shfl_sync(0xffffffffu, r_src, jj + 3);
            float p0 = __shfl_sync(0xffffffffu, p_st, head);
            float p1 = __shfl_sync(0xffffffffu, p_st, 8 + head);
            float p2 = __shfl_sync(0xffffffffu, p_st, 16 + head);
            float p3 = __shfl_sync(0xffffffffu, p_st, 24 + head);
            uint4 u0 = *reinterpret_cast<const uint4*>(g_h1h + (size_t)s0 * D1 + lane * 8);
            uint4 u1 = *reinterpret_cast<const uint4*>(g_h1h + (size_t)s1 * D1 + lane * 8);
            uint4 u2 = *reinterpret_cast<const uint4*>(g_h1h + (size_t)s2 * D1 + lane * 8);
            uint4 u3 = *reinterpret_cast<const uint4*>(g_h1h + (size_t)s3 * D1 + lane * 8);
            denom += (p0 + p1) + (p2 + p3);
            float2 f;
            f = __half22float2(*reinterpret_cast<__half2*>(&u0.x)); acc[0] += p0 * f.x; acc[1] += p0 * f.y;
            f = __half22float2(*reinterpret_cast<__half2*>(&u0.y)); acc[2] += p0 * f.x; acc[3] += p0 * f.y;
            f = __half22float2(*reinterpret_cast<__half2*>(&u0.z)); acc[4] += p0 * f.x; acc[5] += p0 * f.y;
            f = __half22float2(*reinterpret_cast<__half2*>(&u0.w)); acc[6] += p0 * f.x; acc[7] += p0 * f.y;
            f = __half22float2(*reinterpret_cast<__half2*>(&u1.x)); acc[0] += p1 * f.x; acc[1] += p1 * f.y;
            f = __half22float2(*reinterpret_cast<__half2*>(&u1.y)); acc[2] += p1 * f.x; acc[3] += p1 * f.y;
            f = __half22float2(*reinterpret_cast<__half2*>(&u1.z)); acc[4] += p1 * f.x; acc[5] += p1 * f.y;
            f = __half22float2(*reinterpret_cast<__half2*>(&u1.w)); acc[6] += p1 * f.x; acc[7] += p1 * f.y;
            f = __half22float2(*reinterpret_cast<__half2*>(&u2.x)); acc[0] += p2 * f.x; acc[1] += p2 * f.y;
            f = __half22float2(*reinterpret_cast<__half2*>(&u2.y)); acc[2] += p2 * f.x; acc[3] += p2 * f.y;
            f = __half22float2(*reinterpret_cast<__half2*>(&u2.z)); acc[4] += p2 * f.x; acc[5] += p2 * f.y;
            f = __half22float2(*reinterpret_cast<__half2*>(&u2.w)); acc[6] += p2 * f.x; acc[7] += p2 * f.y;
            f = __half22float2(*reinterpret_cast<__half2*>(&u3.x)); acc[0] += p3 * f.x; acc[1] += p3 * f.y;
            f = __half22float2(*reinterpret_cast<__half2*>(&u3.y)); acc[2] += p3 * f.x; acc[3] += p3 * f.y;
            f = __half22float2(*reinterpret_cast<__half2*>(&u3.z)); acc[4] += p3 * f.x; acc[5] += p3 * f.y;
            f = __half22float2(*reinterpret_cast<__half2*>(&u3.w)); acc[6] += p3 * f.x; acc[7] += p3 * f.y;
        }
        float ald_own = __shfl_sync(0xffffffffu, ald_stage, head);
        for (; jj < n; jj++) {
            int s0 = __shfl_sync(0xffffffffu, r_src, jj);
            float p0 = __expf(leaky(g_al_src[(size_t)s0 * 8 + head] + ald_own));
            uint4 u0 = *reinterpret_cast<const uint4*>(g_h1h + (size_t)s0 * D1 + lane * 8);
            denom += p0;
            float2 f;
            f = __half22float2(*reinterpret_cast<__half2*>(&u0.x)); acc[0] += p0 * f.x; acc[1] += p0 * f.y;
            f = __half22float2(*reinterpret_cast<__half2*>(&u0.y)); acc[2] += p0 * f.x; acc[3] += p0 * f.y;
            f = __half22float2(*reinterpret_cast<__half2*>(&u0.z)); acc[4] += p0 * f.x; acc[5] += p0 * f.y;
            f = __half22float2(*reinterpret_cast<__half2*>(&u0.w)); acc[6] += p0 * f.x; acc[7] += p0 * f.y;
        }
    }

    float inv = 1.0f / (denom + 1e-16f);
    float o[8];
#pragma unroll
    for (int j = 0; j < 8; j++) {
        float v = acc[j] * inv + b1[lane * 8 + j];
        o[j] = v > 0.0f ? v : expm1f(v);       // fused ELU
    }
    uint4 st;
    st.x = h2_as_u32(__float22half2_rn(make_float2(o[0], o[1])));
    st.y = h2_as_u32(__float22half2_rn(make_float2(o[2], o[3])));
    st.z = h2_as_u32(__float22half2_rn(make_float2(o[4], o[5])));
    st.w = h2_as_u32(__float22half2_rn(make_float2(o[6], o[7])));
    *reinterpret_cast<uint4*>(g_out1h + (size_t)dst * D1 + lane * 8) = st;
}

// ================= fused softmax + aggregation, layer 2 =================
__global__ __launch_bounds__(256)
void fused_agg2(const float* __restrict__ b2, float* __restrict__ out) {
    int dst = (blockIdx.x * 256 + threadIdx.x) >> 5;
    int lane = threadIdx.x & 31;
    if (dst >= NN) return;
    float ald = g_al2d[dst];
    int start = g_off[dst];
    int deg = g_deg[dst];

    float acc0 = 0.0f, acc1 = 0.0f, denom = 0.0f;
    for (int base = 0; base < deg; base += 32) {
        int n = min(32, deg - base);
        int r_src = 0;
        float r_p = 0.0f;
        if (lane < n) {
            r_src = g_esrc[start + base + lane];
            r_p = __expf(leaky(g_al2s[r_src] + ald));
        }
        int j = 0;
        for (; j + 3 < n; j += 4) {
            int s0 = __shfl_sync(0xffffffffu, r_src, j);
            int s1 = __shfl_sync(0xffffffffu, r_src, j + 1);
            int s2 = __shfl_sync(0xffffffffu, r_src, j + 2);
            int s3 = __shfl_sync(0xffffffffu, r_src, j + 3);
            float p0 = __shfl_sync(0xffffffffu, r_p, j);
            float p1 = __shfl_sync(0xffffffffu, r_p, j + 1);
            float p2 = __shfl_sync(0xffffffffu, r_p, j + 2);
            float p3 = __shfl_sync(0xffffffffu, r_p, j + 3);
            denom += (p0 + p1) + (p2 + p3);
            if (lane < 20) {
                uint32_t h0 = *reinterpret_cast<const uint32_t*>(g_h2h + (size_t)s0 * NCLS + 2 * lane);
                uint32_t h1 = *reinterpret_cast<const uint32_t*>(g_h2h + (size_t)s1 * NCLS + 2 * lane);
                uint32_t h2 = *reinterpret_cast<const uint32_t*>(g_h2h + (size_t)s2 * NCLS + 2 * lane);
                uint32_t h3 = *reinterpret_cast<const uint32_t*>(g_h2h + (size_t)s3 * NCLS + 2 * lane);
                float2 f0 = __half22float2(*reinterpret_cast<__half2*>(&h0));
                float2 f1 = __half22float2(*reinterpret_cast<__half2*>(&h1));
                float2 f2 = __half22float2(*reinterpret_cast<__half2*>(&h2));
                float2 f3 = __half22float2(*reinterpret_cast<__half2*>(&h3));
                acc0 += p0 * f0.x + p1 * f1.x + p2 * f2.x + p3 * f3.x;
                acc1 += p0 * f0.y + p1 * f1.y + p2 * f2.y + p3 * f3.y;
            }
        }
        for (; j < n; j++) {
            int s0 = __shfl_sync(0xffffffffu, r_src, j);
            float p0 = __shfl_sync(0xffffffffu, r_p, j);
            denom += p0;
            if (lane < 20) {
                uint32_t h0 = *reinterpret_cast<const uint32_t*>(g_h2h + (size_t)s0 * NCLS + 2 * lane);
                float2 f0 = __half22float2(*reinterpret_cast<__half2*>(&h0));
                acc0 += p0 * f0.x;
                acc1 += p0 * f0.y;
            }
        }
    }
    if (lane < 20) {
        float inv = 1.0f / (denom + 1e-16f);
        float2 v = make_float2(acc0 * inv + b2[2 * lane],
                               acc1 * inv + b2[2 * lane + 1]);
        *reinterpret_cast<float2*>(out + (size_t)dst * NCLS + 2 * lane) = v;
    }
}

// ---------------- launch ----------------
extern "C" void kernel_launch(void* const* d_in, const int* in_sizes, int n_in,
                              void* d_out, int out_size) {
    const float* x        = (const float*)d_in[0];
    const int*   ei       = (const int*)  d_in[1];
    const float* W1       = (const float*)d_in[2];
    const float* att_src1 = (const float*)d_in[3];
    const float* att_dst1 = (const float*)d_in[4];
    const float* b1       = (const float*)d_in[5];
    const float* W2       = (const float*)d_in[6];
    const float* att_src2 = (const float*)d_in[7];
    const float* att_dst2 = (const float*)d_in[8];
    const float* b2       = (const float*)d_in[9];
    float* out = (float*)d_out;

    __half *p_h1h, *p_out1h, *p_h2h;
    float *p_al2s, *p_al2d, *p_als, *p_ald;
    cudaGetSymbolAddress((void**)&p_h1h,   g_h1h);
    cudaGetSymbolAddress((void**)&p_out1h, g_out1h);
    cudaGetSymbolAddress((void**)&p_h2h,   g_h2h);
    cudaGetSymbolAddress((void**)&p_al2s,  g_al2s);
    cudaGetSymbolAddress((void**)&p_al2d,  g_al2d);
    cudaGetSymbolAddress((void**)&p_als,   g_al_src);
    cudaGetSymbolAddress((void**)&p_ald,   g_al_dst);

    // Side stream for CSR build (fork-join, graph-capture safe)
    cudaStream_t s2;
    cudaEvent_t evFork, evJoin;
    cudaStreamCreateWithFlags(&s2, cudaStreamNonBlocking);
    cudaEventCreateWithFlags(&evFork, cudaEventDisableTiming);
    cudaEventCreateWithFlags(&evJoin, cudaEventDisableTiming);

    // ---- fork: CSR build on s2 (4 kernels), overlapped with GEMM1 ----
    cudaEventRecord(evFork, 0);
    cudaStreamWaitEvent(s2, evFork, 0);

    zero_deg_kernel<<<NB_SCAN, 256, 0, s2>>>();
    hist_kernel<<<(ETOT + 255) / 256, 256, 0, s2>>>(ei);
    scan_all_kernel<<<1, 1024, 0, s2>>>();
    scatter_kernel<<<(ETOT + 255) / 256, 256, 0, s2>>>(ei);
    cudaEventRecord(evJoin, s2);

    // 1. GEMM1 (fp16 HMMA + ldmatrix, fp32 acc, fused per-head al1 dots)
    {
        dim3 grid(D1 / 128, (NN + 127) / 128);
        fp16_gemm1<<<grid, 256>>>(x, W1, p_h1h, NN,
                                  att_src1, att_dst1, p_als, p_ald);
    }

    // ---- join: agg1 needs the CSR ----
    cudaStreamWaitEvent(0, evJoin, 0);

    // 2. fused softmax + aggregation + bias + ELU (layer 1), fp16 out1
    fused_agg1<<<(NN * 32 + 255) / 256, 256>>>(b1);

    // 3. GEMM2 (fp16 HMMA, BM=128, N-tile 40, fused per-row al2 dots)
    {
        dim3 grid(1, (NN + 127) / 128);
        fp16_gemm2<<<grid, 256>>>(p_out1h, W2, p_h2h, NN,
                                  att_src2, att_dst2, p_al2s, p_al2d);
    }

    // 4. fused softmax + aggregation + bias (layer 2) -> d_out
    fused_agg2<<<(NN * 32 + 255) / 256, 256>>>(b2, out);

    cudaEventDestroy(evFork);
    cudaEventDestroy(evJoin);
    cudaStreamDestroy(s2);
}

// round 17
// speedup vs baseline: 1.3193x; 1.3193x over previous
#include <cuda_runtime.h>
#include <cuda_fp16.h>
#include <math.h>
#include <stdint.h>

// Problem constants (fixed-shape problem)
#define NN      50000
#define EE      800000
#define ETOT    (EE + NN)      // self-loops appended
#define IN_CH   512
#define HID     32
#define HEADS   8
#define D1      (HID * HEADS)  // 256
#define NCLS    40
#define NEG_SLOPE 0.2f
#define NB_SCAN ((NN + 255) / 256)   // 196

// ---------------- scratch (device globals, no allocs allowed) ----------------
__device__ __align__(128) __half g_h1h[NN * D1];         // 25.6 MB (fp16 h1)
__device__ __align__(128) __half g_out1h[NN * D1];       // 25.6 MB (fp16 post-ELU)
__device__ __align__(128) float g_al_src[NN * HEADS];
__device__ __align__(128) float g_al_dst[NN * HEADS];
__device__ __align__(128) __half g_h2h[NN * NCLS];       // 4 MB (fp16 h2)
__device__ __align__(128) float g_al2s[NN];
__device__ __align__(128) float g_al2d[NN];
// CSR-by-dst
__device__ int g_deg[NN];
__device__ int g_off[NN];
__device__ int g_wpos[NN];
__device__ int g_esrc[ETOT];
__device__ int g_bsum[NB_SCAN];
__device__ int g_bsumx[NB_SCAN];

// ---------------- helpers ----------------
__device__ __forceinline__ float leaky(float x) {
    return x > 0.0f ? x : NEG_SLOPE * x;
}

__device__ __forceinline__ uint32_t h2_as_u32(__half2 h) {
    return *reinterpret_cast<uint32_t*>(&h);
}

__device__ __forceinline__ void mma_f16(float c[4], uint32_t a0, uint32_t a1,
                                        uint32_t a2, uint32_t a3,
                                        uint32_t b0, uint32_t b1) {
    asm volatile(
        "mma.sync.aligned.m16n8k16.row.col.f32.f16.f16.f32 "
        "{%0,%1,%2,%3}, {%4,%5,%6,%7}, {%8,%9}, {%0,%1,%2,%3};\n"
        : "+f"(c[0]), "+f"(c[1]), "+f"(c[2]), "+f"(c[3])
        : "r"(a0), "r"(a1), "r"(a2), "r"(a3), "r"(b0), "r"(b1));
}

__device__ __forceinline__ void ldsm_x4(uint32_t& r0, uint32_t& r1,
                                        uint32_t& r2, uint32_t& r3,
                                        uint32_t addr) {
    asm volatile("ldmatrix.sync.aligned.m8n8.x4.shared.b16 {%0,%1,%2,%3}, [%4];"
                 : "=r"(r0), "=r"(r1), "=r"(r2), "=r"(r3) : "r"(addr));
}

__device__ __forceinline__ void ldsm_x2_trans(uint32_t& r0, uint32_t& r1,
                                              uint32_t addr) {
    asm volatile("ldmatrix.sync.aligned.m8n8.x2.trans.shared.b16 {%0,%1}, [%2];"
                 : "=r"(r0), "=r"(r1) : "r"(addr));
}

// =====================================================================
// fp16 HMMA GEMM1 (proven R12): C[M,256] = A[M,512] @ B[512,256].
// =====================================================================
__global__ __launch_bounds__(256)
void fp16_gemm1(const float* __restrict__ A, const float* __restrict__ B,
                __half* __restrict__ C, int M,
                const float* __restrict__ as1, const float* __restrict__ ad1,
                float* __restrict__ als, float* __restrict__ ald) {
    constexpr int KTOT = IN_CH;    // 512
    constexpr int NCOLS = D1;      // 256
    constexpr int ASTR = 40;
    constexpr int BSTR = 136;
    __shared__ __align__(16) __half As[2][128][ASTR];
    __shared__ __align__(16) __half Bs[2][32][BSTR];

    const int tid = threadIdx.x;
    const int lane = tid & 31;
    const int warpId = tid >> 5;
    const int br = blockIdx.y;
    const int bc = blockIdx.x;

    const int wm = (warpId & 3) * 32;
    const int wn = (warpId >> 2) * 64;
    const int g = lane >> 2;
    const int t = lane & 3;

    float acc[2][8][4];
#pragma unroll
    for (int mi = 0; mi < 2; mi++)
#pragma unroll
        for (int ni = 0; ni < 8; ni++)
#pragma unroll
            for (int r = 0; r < 4; r++) acc[mi][ni][r] = 0.0f;

    const int a_m = tid >> 3;
    const int a_k = (tid & 7) * 4;
    const int b_n = (tid & 31) * 4;
    const int b_k = tid >> 5;

    float4 ra[4], rb[4];

    auto loadA = [&](int r, int k0) -> float4 {
        int grow = br * 128 + r * 32 + a_m;
        if (grow >= M) return make_float4(0.f, 0.f, 0.f, 0.f);
        return *reinterpret_cast<const float4*>(A + (size_t)grow * KTOT + k0 + a_k);
    };
    auto loadB = [&](int r, int k0) -> float4 {
        return *reinterpret_cast<const float4*>(
            B + (size_t)(k0 + r * 8 + b_k) * NCOLS + bc * 128 + b_n);
    };
    auto stageChunk = [&](int nb) {
#pragma unroll
        for (int r = 0; r < 4; r++) {
            __half2 h0 = __float22half2_rn(make_float2(ra[r].x, ra[r].y));
            __half2 h1 = __float22half2_rn(make_float2(ra[r].z, ra[r].w));
            uint2 u = make_uint2(h2_as_u32(h0), h2_as_u32(h1));
            *reinterpret_cast<uint2*>(&As[nb][r * 32 + a_m][a_k]) = u;
        }
#pragma unroll
        for (int r = 0; r < 4; r++) {
            __half2 h0 = __float22half2_rn(make_float2(rb[r].x, rb[r].y));
            __half2 h1 = __float22half2_rn(make_float2(rb[r].z, rb[r].w));
            uint2 u = make_uint2(h2_as_u32(h0), h2_as_u32(h1));
            *reinterpret_cast<uint2*>(&Bs[nb][r * 8 + b_k][b_n]) = u;
        }
    };

#pragma unroll
    for (int r = 0; r < 4; r++) { ra[r] = loadA(r, 0); rb[r] = loadB(r, 0); }
    stageChunk(0);
    __syncthreads();
#pragma unroll
    for (int r = 0; r < 4; r++) { ra[r] = loadA(r, 32); rb[r] = loadB(r, 32); }

    const int lg = lane >> 3;
    const int li = lane & 7;
    const int a_frow = ((lg & 1) << 3) + li;
    const int a_fcol = (lg >> 1) << 3;
    const int b_frow = ((lane >> 3) & 1) * 8 + li;

    int buf = 0;
    for (int k0 = 0; k0 < KTOT; k0 += 32) {
        bool has_next = (k0 + 32 < KTOT);
        if (has_next) stageChunk(buf ^ 1);
        if (k0 + 64 < KTOT) {
#pragma unroll
            for (int r = 0; r < 4; r++) { ra[r] = loadA(r, k0 + 64); rb[r] = loadB(r, k0 + 64); }
        }

#pragma unroll
        for (int ks = 0; ks < 2; ks++) {
            const int kk = ks * 16;
            uint32_t a[2][4];
#pragma unroll
            for (int mi = 0; mi < 2; mi++) {
                uint32_t ad = (uint32_t)__cvta_generic_to_shared(
                    &As[buf][wm + mi * 16 + a_frow][kk + a_fcol]);
                ldsm_x4(a[mi][0], a[mi][1], a[mi][2], a[mi][3], ad);
            }
#pragma unroll
            for (int ni = 0; ni < 8; ni++) {
                uint32_t bd = (uint32_t)__cvta_generic_to_shared(
                    &Bs[buf][kk + b_frow][wn + ni * 8]);
                uint32_t b0, b1;
                ldsm_x2_trans(b0, b1, bd);
                mma_f16(acc[0][ni], a[0][0], a[0][1], a[0][2], a[0][3], b0, b1);
                mma_f16(acc[1][ni], a[1][0], a[1][1], a[1][2], a[1][3], b0, b1);
            }
        }
        if (has_next) {
            __syncthreads();
            buf ^= 1;
        }
    }

    // epilogue: store C (fp16)
#pragma unroll
    for (int mi = 0; mi < 2; mi++) {
        int row0 = br * 128 + wm + mi * 16 + g;
        int row1 = row0 + 8;
#pragma unroll
        for (int ni = 0; ni < 8; ni++) {
            int col = bc * 128 + wn + ni * 8 + 2 * t;
            if (row0 < M)
                *reinterpret_cast<__half2*>(C + (size_t)row0 * NCOLS + col) =
                    __float22half2_rn(make_float2(acc[mi][ni][0], acc[mi][ni][1]));
            if (row1 < M)
                *reinterpret_cast<__half2*>(C + (size_t)row1 * NCOLS + col) =
                    __float22half2_rn(make_float2(acc[mi][ni][2], acc[mi][ni][3]));
        }
    }

    // fused per-head attention dots (32-col head groups)
#pragma unroll
    for (int mi = 0; mi < 2; mi++) {
#pragma unroll
        for (int hl = 0; hl < 2; hl++) {
            float ps0 = 0.f, ps1 = 0.f, pd0 = 0.f, pd1 = 0.f;
#pragma unroll
            for (int nq = 0; nq < 4; nq++) {
                int ni = hl * 4 + nq;
                int gcol = bc * 128 + wn + ni * 8 + 2 * t;
                float a0 = as1[gcol], a1 = as1[gcol + 1];
                float d0 = ad1[gcol], d1 = ad1[gcol + 1];
                ps0 += acc[mi][ni][0] * a0 + acc[mi][ni][1] * a1;
                ps1 += acc[mi][ni][2] * a0 + acc[mi][ni][3] * a1;
                pd0 += acc[mi][ni][0] * d0 + acc[mi][ni][1] * d1;
                pd1 += acc[mi][ni][2] * d0 + acc[mi][ni][3] * d1;
            }
#pragma unroll
            for (int off = 1; off < 4; off <<= 1) {
                ps0 += __shfl_xor_sync(0xffffffffu, ps0, off);
                ps1 += __shfl_xor_sync(0xffffffffu, ps1, off);
                pd0 += __shfl_xor_sync(0xffffffffu, pd0, off);
                pd1 += __shfl_xor_sync(0xffffffffu, pd1, off);
            }
            if (t == 0) {
                int head = ((bc * 128 + wn) >> 5) + hl;
                int row0 = br * 128 + wm + mi * 16 + g;
                int row1 = row0 + 8;
                if (row0 < M) {
                    als[(size_t)row0 * HEADS + head] = ps0;
                    ald[(size_t)row0 * HEADS + head] = pd0;
                }
                if (row1 < M) {
                    als[(size_t)row1 * HEADS + head] = ps1;
                    ald[(size_t)row1 * HEADS + head] = pd1;
                }
            }
        }
    }
}

// =====================================================================
// fp16 HMMA GEMM2 (R15): C[M,40] = A[M,256](fp16) @ B[256,40].
// BM=128, 8 warps x 16 rows, N tile = 40 exact. Fused per-row al2 dots.
// =====================================================================
__global__ __launch_bounds__(256)
void fp16_gemm2(const __half* __restrict__ A, const float* __restrict__ B,
                __half* __restrict__ C, int M,
                const float* __restrict__ as2, const float* __restrict__ ad2,
                float* __restrict__ als, float* __restrict__ ald) {
    constexpr int KTOT = D1;       // 256
    constexpr int NCOLS = NCLS;    // 40
    constexpr int BM = 128;
    constexpr int NI = 5;
    constexpr int ASTR = 40;
    constexpr int BSTR = 72;
    __shared__ __align__(16) __half As[BM][ASTR];
    __shared__ __align__(16) __half Bs[32][BSTR];

    const int tid = threadIdx.x;
    const int lane = tid & 31;
    const int warpId = tid >> 5;
    const int br = blockIdx.y;

    const int wm = warpId * 16;
    const int g = lane >> 2;
    const int t = lane & 3;

    float acc[NI][4];
#pragma unroll
    for (int ni = 0; ni < NI; ni++)
#pragma unroll
        for (int r = 0; r < 4; r++) acc[ni][r] = 0.0f;

    const int a_m = tid >> 3;
    const int a_k = (tid & 7) * 4;
    const int b_n = (tid & 15) * 4;
    const int b_k = tid >> 4;

    uint2 ra[4];
    float4 rb[2];

    auto loadA = [&](int r, int k0) -> uint2 {
        int grow = br * BM + r * 32 + a_m;
        if (grow >= M) return make_uint2(0u, 0u);
        return *reinterpret_cast<const uint2*>(A + (size_t)grow * KTOT + k0 + a_k);
    };
    auto loadBg = [&](int r, int k0) -> float4 {
        if (b_n >= NCOLS) return make_float4(0.f, 0.f, 0.f, 0.f);
        return *reinterpret_cast<const float4*>(
            B + (size_t)(k0 + r * 16 + b_k) * NCOLS + b_n);
    };
    auto stageChunk = [&]() {
#pragma unroll
        for (int r = 0; r < 4; r++)
            *reinterpret_cast<uint2*>(&As[r * 32 + a_m][a_k]) = ra[r];
#pragma unroll
        for (int r = 0; r < 2; r++) {
            __half2 h0 = __float22half2_rn(make_float2(rb[r].x, rb[r].y));
            __half2 h1 = __float22half2_rn(make_float2(rb[r].z, rb[r].w));
            uint2 u = make_uint2(h2_as_u32(h0), h2_as_u32(h1));
            *reinterpret_cast<uint2*>(&Bs[r * 16 + b_k][b_n]) = u;
        }
    };

#pragma unroll
    for (int r = 0; r < 4; r++) ra[r] = loadA(r, 0);
#pragma unroll
    for (int r = 0; r < 2; r++) rb[r] = loadBg(r, 0);

    const int lg = lane >> 3;
    const int li = lane & 7;
    const int a_frow = ((lg & 1) << 3) + li;
    const int a_fcol = (lg >> 1) << 3;
    const int b_frow = ((lane >> 3) & 1) * 8 + li;

    for (int k0 = 0; k0 < KTOT; k0 += 32) {
        stageChunk();
        __syncthreads();

        if (k0 + 32 < KTOT) {
#pragma unroll
            for (int r = 0; r < 4; r++) ra[r] = loadA(r, k0 + 32);
#pragma unroll
            for (int r = 0; r < 2; r++) rb[r] = loadBg(r, k0 + 32);
        }

#pragma unroll
        for (int ks = 0; ks < 2; ks++) {
            const int kk = ks * 16;
            uint32_t a0, a1, a2, a3;
            uint32_t ad = (uint32_t)__cvta_generic_to_shared(
                &As[wm + a_frow][kk + a_fcol]);
            ldsm_x4(a0, a1, a2, a3, ad);
#pragma unroll
            for (int ni = 0; ni < NI; ni++) {
                uint32_t bd = (uint32_t)__cvta_generic_to_shared(
                    &Bs[kk + b_frow][ni * 8]);
                uint32_t b0, b1;
                ldsm_x2_trans(b0, b1, bd);
                mma_f16(acc[ni], a0, a1, a2, a3, b0, b1);
            }
        }
        __syncthreads();
    }

    // epilogue: store C (fp16)
    {
        int row0 = br * BM + wm + g;
        int row1 = row0 + 8;
#pragma unroll
        for (int ni = 0; ni < NI; ni++) {
            int col = ni * 8 + 2 * t;
            if (row0 < M)
                *reinterpret_cast<__half2*>(C + (size_t)row0 * NCOLS + col) =
                    __float22half2_rn(make_float2(acc[ni][0], acc[ni][1]));
            if (row1 < M)
                *reinterpret_cast<__half2*>(C + (size_t)row1 * NCOLS + col) =
                    __float22half2_rn(make_float2(acc[ni][2], acc[ni][3]));
        }
    }

    // fused per-row attention dots
    {
        float ps0 = 0.f, ps1 = 0.f, pd0 = 0.f, pd1 = 0.f;
#pragma unroll
        for (int ni = 0; ni < NI; ni++) {
            int col = ni * 8 + 2 * t;
            float a0 = as2[col], a1 = as2[col + 1];
            float d0 = ad2[col], d1 = ad2[col + 1];
            ps0 += acc[ni][0] * a0 + acc[ni][1] * a1;
            ps1 += acc[ni][2] * a0 + acc[ni][3] * a1;
            pd0 += acc[ni][0] * d0 + acc[ni][1] * d1;
            pd1 += acc[ni][2] * d0 + acc[ni][3] * d1;
        }
#pragma unroll
        for (int off = 1; off < 4; off <<= 1) {
            ps0 += __shfl_xor_sync(0xffffffffu, ps0, off);
            ps1 += __shfl_xor_sync(0xffffffffu, ps1, off);
            pd0 += __shfl_xor_sync(0xffffffffu, pd0, off);
            pd1 += __shfl_xor_sync(0xffffffffu, pd1, off);
        }
        if (t == 0) {
            int row0 = br * BM + wm + g;
            int row1 = row0 + 8;
            if (row0 < M) { als[row0] = ps0; ald[row0] = pd0; }
            if (row1 < M) { als[row1] = ps1; ald[row1] = pd1; }
        }
    }
}

// ================= CSR build =================
__global__ void zero_deg_kernel() {
    int i = blockIdx.x * blockDim.x + threadIdx.x;
    if (i < NN) g_deg[i] = 0;
}

__global__ void hist_kernel(const int* __restrict__ ei) {
    int e = blockIdx.x * blockDim.x + threadIdx.x;
    if (e >= ETOT) return;
    int dst = (e < EE) ? ei[EE + e] : e - EE;
    atomicAdd(&g_deg[dst], 1);
}

__global__ void scan1_kernel() {
    __shared__ int s[256];
    int i = blockIdx.x * 256 + threadIdx.x;
    int v = (i < NN) ? g_deg[i] : 0;
    s[threadIdx.x] = v;
    __syncthreads();
#pragma unroll
    for (int d = 1; d < 256; d <<= 1) {
        int t = (threadIdx.x >= d) ? s[threadIdx.x - d] : 0;
        __syncthreads();
        s[threadIdx.x] += t;
        __syncthreads();
    }
    if (i < NN) g_off[i] = s[threadIdx.x] - v;   // exclusive
    if (threadIdx.x == 255) g_bsum[blockIdx.x] = s[255];
}

__global__ void scan2_kernel() {
    __shared__ int s[256];
    int v = (threadIdx.x < NB_SCAN) ? g_bsum[threadIdx.x] : 0;
    s[threadIdx.x] = v;
    __syncthreads();
#pragma unroll
    for (int d = 1; d < 256; d <<= 1) {
        int t = (threadIdx.x >= d) ? s[threadIdx.x - d] : 0;
        __syncthreads();
        s[threadIdx.x] += t;
        __syncthreads();
    }
    if (threadIdx.x < NB_SCAN) g_bsumx[threadIdx.x] = s[threadIdx.x] - v;
}

__global__ void scan3_kernel() {
    int i = blockIdx.x * 256 + threadIdx.x;
    if (i < NN) {
        int o = g_off[i] + g_bsumx[blockIdx.x];
        g_off[i] = o;
        g_wpos[i] = o;
    }
}

__global__ void scatter_kernel(const int* __restrict__ ei) {
    int e = blockIdx.x * blockDim.x + threadIdx.x;
    if (e >= ETOT) return;
    int src, dst;
    if (e < EE) { src = ei[e]; dst = ei[EE + e]; }
    else        { src = dst = e - EE; }
    int pos = atomicAdd(&g_wpos[dst], 1);
    g_esrc[pos] = src;
}

// ================= fused softmax + aggregation, layer 1 =================
// One warp per dst. Groups of 4 edges: p staged across lanes
// (lane = edge*8+head), one exp per (edge,head); exp off serial chain.
__global__ __launch_bounds__(256)
void fused_agg1(const float* __restrict__ b1) {
    int dst = (blockIdx.x * 256 + threadIdx.x) >> 5;
    int lane = threadIdx.x & 31;
    if (dst >= NN) return;
    int head = lane >> 2;
    int h8 = lane & 7;
    float ald_stage = g_al_dst[(size_t)dst * 8 + h8];
    int start = g_off[dst];
    int deg = g_deg[dst];

    float acc[8];
#pragma unroll
    for (int j = 0; j < 8; j++) acc[j] = 0.0f;
    float denom = 0.0f;

    for (int base = 0; base < deg; base += 32) {
        int n = min(32, deg - base);
        int r_src = (lane < n) ? g_esrc[start + base + lane] : 0;

        int jj = 0;
        for (; jj + 3 < n; jj += 4) {
            int le = jj + (lane >> 3);
            int src_st = __shfl_sync(0xffffffffu, r_src, le);
            float p_st = __expf(leaky(g_al_src[(size_t)src_st * 8 + h8] + ald_stage));
            int s0 = __shfl_sync(0xffffffffu, r_src, jj);
            int s1 = __shfl_sync(0xffffffffu, r_src, jj + 1);
            int s2 = __shfl_sync(0xffffffffu, r_src, jj + 2);
            int s3 = __shfl_sync(0xffffffffu, r_src, jj + 3);
            float p0 = __shfl_sync(0xffffffffu, p_st, head);
            float p1 = __shfl_sync(0xffffffffu, p_st, 8 + head);
            float p2 = __shfl_sync(0xffffffffu, p_st, 16 + head);
            float p3 = __shfl_sync(0xffffffffu, p_st, 24 + head);
            uint4 u0 = *reinterpret_cast<const uint4*>(g_h1h + (size_t)s0 * D1 + lane * 8);
            uint4 u1 = *reinterpret_cast<const uint4*>(g_h1h + (size_t)s1 * D1 + lane * 8);
            uint4 u2 = *reinterpret_cast<const uint4*>(g_h1h + (size_t)s2 * D1 + lane * 8);
            uint4 u3 = *reinterpret_cast<const uint4*>(g_h1h + (size_t)s3 * D1 + lane * 8);
            denom += (p0 + p1) + (p2 + p3);
            float2 f;
            f = __half22float2(*reinterpret_cast<__half2*>(&u0.x)); acc[0] += p0 * f.x; acc[1] += p0 * f.y;
            f = __half22float2(*reinterpret_cast<__half2*>(&u0.y)); acc[2] += p0 * f.x; acc[3] += p0 * f.y;
            f = __half22float2(*reinterpret_cast<__half2*>(&u0.z)); acc[4] += p0 * f.x; acc[5] += p0 * f.y;
            f = __half22float2(*reinterpret_cast<__half2*>(&u0.w)); acc[6] += p0 * f.x; acc[7] += p0 * f.y;
            f = __half22float2(*reinterpret_cast<__half2*>(&u1.x)); acc[0] += p1 * f.x; acc[1] += p1 * f.y;
            f = __half22float2(*reinterpret_cast<__half2*>(&u1.y)); acc[2] += p1 * f.x; acc[3] += p1 * f.y;
            f = __half22float2(*reinterpret_cast<__half2*>(&u1.z)); acc[4] += p1 * f.x; acc[5] += p1 * f.y;
            f = __half22float2(*reinterpret_cast<__half2*>(&u1.w)); acc[6] += p1 * f.x; acc[7] += p1 * f.y;
            f = __half22float2(*reinterpret_cast<__half2*>(&u2.x)); acc[0] += p2 * f.x; acc[1] += p2 * f.y;
            f = __half22float2(*reinterpret_cast<__half2*>(&u2.y)); acc[2] += p2 * f.x; acc[3] += p2 * f.y;
            f = __half22float2(*reinterpret_cast<__half2*>(&u2.z)); acc[4] += p2 * f.x; acc[5] += p2 * f.y;
            f = __half22float2(*reinterpret_cast<__half2*>(&u2.w)); acc[6] += p2 * f.x; acc[7] += p2 * f.y;
            f = __half22float2(*reinterpret_cast<__half2*>(&u3.x)); acc[0] += p3 * f.x; acc[1] += p3 * f.y;
            f = __half22float2(*reinterpret_cast<__half2*>(&u3.y)); acc[2] += p3 * f.x; acc[3] += p3 * f.y;
            f = __half22float2(*reinterpret_cast<__half2*>(&u3.z)); acc[4] += p3 * f.x; acc[5] += p3 * f.y;
            f = __half22float2(*reinterpret_cast<__half2*>(&u3.w)); acc[6] += p3 * f.x; acc[7] += p3 * f.y;
        }
        float ald_own = __shfl_sync(0xffffffffu, ald_stage, head);
        for (; jj < n; jj++) {
            int s0 = __shfl_sync(0xffffffffu, r_src, jj);
            float p0 = __expf(leaky(g_al_src[(size_t)s0 * 8 + head] + ald_own));
            uint4 u0 = *reinterpret_cast<const uint4*>(g_h1h + (size_t)s0 * D1 + lane * 8);
            denom += p0;
            float2 f;
            f = __half22float2(*reinterpret_cast<__half2*>(&u0.x)); acc[0] += p0 * f.x; acc[1] += p0 * f.y;
            f = __half22float2(*reinterpret_cast<__half2*>(&u0.y)); acc[2] += p0 * f.x; acc[3] += p0 * f.y;
            f = __half22float2(*reinterpret_cast<__half2*>(&u0.z)); acc[4] += p0 * f.x; acc[5] += p0 * f.y;
            f = __half22float2(*reinterpret_cast<__half2*>(&u0.w)); acc[6] += p0 * f.x; acc[7] += p0 * f.y;
        }
    }

    float inv = 1.0f / (denom + 1e-16f);
    float o[8];
#pragma unroll
    for (int j = 0; j < 8; j++) {
        float v = acc[j] * inv + b1[lane * 8 + j];
        o[j] = v > 0.0f ? v : expm1f(v);       // fused ELU
    }
    uint4 st;
    st.x = h2_as_u32(__float22half2_rn(make_float2(o[0], o[1])));
    st.y = h2_as_u32(__float22half2_rn(make_float2(o[2], o[3])));
    st.z = h2_as_u32(__float22half2_rn(make_float2(o[4], o[5])));
    st.w = h2_as_u32(__float22half2_rn(make_float2(o[6], o[7])));
    *reinterpret_cast<uint4*>(g_out1h + (size_t)dst * D1 + lane * 8) = st;
}

// ================= fused softmax + aggregation, layer 2 =================
__global__ __launch_bounds__(256)
void fused_agg2(const float* __restrict__ b2, float* __restrict__ out) {
    int dst = (blockIdx.x * 256 + threadIdx.x) >> 5;
    int lane = threadIdx.x & 31;
    if (dst >= NN) return;
    float ald = g_al2d[dst];
    int start = g_off[dst];
    int deg = g_deg[dst];

    float acc0 = 0.0f, acc1 = 0.0f, denom = 0.0f;
    for (int base = 0; base < deg; base += 32) {
        int n = min(32, deg - base);
        int r_src = 0;
        float r_p = 0.0f;
        if (lane < n) {
            r_src = g_esrc[start + base + lane];
            r_p = __expf(leaky(g_al2s[r_src] + ald));
        }
        int j = 0;
        for (; j + 3 < n; j += 4) {
            int s0 = __shfl_sync(0xffffffffu, r_src, j);
            int s1 = __shfl_sync(0xffffffffu, r_src, j + 1);
            int s2 = __shfl_sync(0xffffffffu, r_src, j + 2);
            int s3 = __shfl_sync(0xffffffffu, r_src, j + 3);
            float p0 = __shfl_sync(0xffffffffu, r_p, j);
            float p1 = __shfl_sync(0xffffffffu, r_p, j + 1);
            float p2 = __shfl_sync(0xffffffffu, r_p, j + 2);
            float p3 = __shfl_sync(0xffffffffu, r_p, j + 3);
            denom += (p0 + p1) + (p2 + p3);
            if (lane < 20) {
                uint32_t h0 = *reinterpret_cast<const uint32_t*>(g_h2h + (size_t)s0 * NCLS + 2 * lane);
                uint32_t h1 = *reinterpret_cast<const uint32_t*>(g_h2h + (size_t)s1 * NCLS + 2 * lane);
                uint32_t h2 = *reinterpret_cast<const uint32_t*>(g_h2h + (size_t)s2 * NCLS + 2 * lane);
                uint32_t h3 = *reinterpret_cast<const uint32_t*>(g_h2h + (size_t)s3 * NCLS + 2 * lane);
                float2 f0 = __half22float2(*reinterpret_cast<__half2*>(&h0));
                float2 f1 = __half22float2(*reinterpret_cast<__half2*>(&h1));
                float2 f2 = __half22float2(*reinterpret_cast<__half2*>(&h2));
                float2 f3 = __half22float2(*reinterpret_cast<__half2*>(&h3));
                acc0 += p0 * f0.x + p1 * f1.x + p2 * f2.x + p3 * f3.x;
                acc1 += p0 * f0.y + p1 * f1.y + p2 * f2.y + p3 * f3.y;
            }
        }
        for (; j < n; j++) {
            int s0 = __shfl_sync(0xffffffffu, r_src, j);
            float p0 = __shfl_sync(0xffffffffu, r_p, j);
            denom += p0;
            if (lane < 20) {
                uint32_t h0 = *reinterpret_cast<const uint32_t*>(g_h2h + (size_t)s0 * NCLS + 2 * lane);
                float2 f0 = __half22float2(*reinterpret_cast<__half2*>(&h0));
                acc0 += p0 * f0.x;
                acc1 += p0 * f0.y;
            }
        }
    }
    if (lane < 20) {
        float inv = 1.0f / (denom + 1e-16f);
        float2 v = make_float2(acc0 * inv + b2[2 * lane],
                               acc1 * inv + b2[2 * lane + 1]);
        *reinterpret_cast<float2*>(out + (size_t)dst * NCLS + 2 * lane) = v;
    }
}

// ---------------- launch ----------------
extern "C" void kernel_launch(void* const* d_in, const int* in_sizes, int n_in,
                              void* d_out, int out_size) {
    const float* x        = (const float*)d_in[0];
    const int*   ei       = (const int*)  d_in[1];
    const float* W1       = (const float*)d_in[2];
    const float* att_src1 = (const float*)d_in[3];
    const float* att_dst1 = (const float*)d_in[4];
    const float* b1       = (const float*)d_in[5];
    const float* W2       = (const float*)d_in[6];
    const float* att_src2 = (const float*)d_in[7];
    const float* att_dst2 = (const float*)d_in[8];
    const float* b2       = (const float*)d_in[9];
    float* out = (float*)d_out;

    __half *p_h1h, *p_out1h, *p_h2h;
    float *p_al2s, *p_al2d, *p_als, *p_ald;
    cudaGetSymbolAddress((void**)&p_h1h,   g_h1h);
    cudaGetSymbolAddress((void**)&p_out1h, g_out1h);
    cudaGetSymbolAddress((void**)&p_h2h,   g_h2h);
    cudaGetSymbolAddress((void**)&p_al2s,  g_al2s);
    cudaGetSymbolAddress((void**)&p_al2d,  g_al2d);
    cudaGetSymbolAddress((void**)&p_als,   g_al_src);
    cudaGetSymbolAddress((void**)&p_ald,   g_al_dst);

    // Side stream for CSR build (fork-join, graph-capture safe)
    cudaStream_t s2;
    cudaEvent_t evFork, evJoin;
    cudaStreamCreateWithFlags(&s2, cudaStreamNonBlocking);
    cudaEventCreateWithFlags(&evFork, cudaEventDisableTiming);
    cudaEventCreateWithFlags(&evJoin, cudaEventDisableTiming);

    // ---- fork: CSR build on s2, overlapped with GEMM1 ----
    cudaEventRecord(evFork, 0);
    cudaStreamWaitEvent(s2, evFork, 0);

    zero_deg_kernel<<<NB_SCAN, 256, 0, s2>>>();
    hist_kernel<<<(ETOT + 255) / 256, 256, 0, s2>>>(ei);
    scan1_kernel<<<NB_SCAN, 256, 0, s2>>>();
    scan2_kernel<<<1, 256, 0, s2>>>();
    scan3_kernel<<<NB_SCAN, 256, 0, s2>>>();
    scatter_kernel<<<(ETOT + 255) / 256, 256, 0, s2>>>(ei);
    cudaEventRecord(evJoin, s2);

    // 1. GEMM1 (fp16 HMMA + ldmatrix, fp32 acc, fused per-head al1 dots)
    {
        dim3 grid(D1 / 128, (NN + 127) / 128);
        fp16_gemm1<<<grid, 256>>>(x, W1, p_h1h, NN,
                                  att_src1, att_dst1, p_als, p_ald);
    }

    // ---- join: agg1 needs the CSR ----
    cudaStreamWaitEvent(0, evJoin, 0);

    // 2. fused softmax + aggregation + bias + ELU (layer 1), fp16 out1
    fused_agg1<<<(NN * 32 + 255) / 256, 256>>>(b1);

    // 3. GEMM2 (fp16 HMMA, BM=128, N-tile 40, fused per-row al2 dots)
    {
        dim3 grid(1, (NN + 127) / 128);
        fp16_gemm2<<<grid, 256>>>(p_out1h, W2, p_h2h, NN,
                                  att_src2, att_dst2, p_al2s, p_al2d);
    }

    // 4. fused softmax + aggregation + bias (layer 2) -> d_out
    fused_agg2<<<(NN * 32 + 255) / 256, 256>>>(b2, out);

    cudaEventDestroy(evFork);
    cudaEventDestroy(evJoin);
    cudaStreamDestroy(s2);
}